// round 12
// baseline (speedup 1.0000x reference)
#include <cuda_runtime.h>
#include <cuda_fp16.h>

#define N_NODES 100000
#define N_EDGES_MAX 1600000
#define IN_F    256
#define HID_F   128
#define OUT_F   32

#define SCAN_BLK 1024
#define N_SCAN_BLOCKS ((N_NODES + SCAN_BLK - 1) / SCAN_BLK)   // 98

// Scratch: __device__ globals (no allocation allowed anywhere).
__device__ __half g_h0h[(size_t)N_NODES * HID_F];  // x @ W1   (fp16 payload)
__device__ __half g_h1h[(size_t)N_NODES * HID_F];  // spmm1 out (fp16 payload)
__device__ __half g_h2h[(size_t)N_NODES * OUT_F];  // relu(h1) @ W2 (fp16)

// CSR scratch
__device__ int       g_counts[N_NODES];
__device__ int       g_row_ptr[N_NODES + 1];
__device__ int       g_cursor[N_NODES];
__device__ int       g_partials[N_SCAN_BLOCKS];
__device__ long long g_edges[N_EDGES_MAX];   // packed: low32=col, high32=val bits

// ---------------------------------------------------------------------------
// CSR build
// ---------------------------------------------------------------------------
__global__ void zero_counts_kernel() {
    int i = blockIdx.x * blockDim.x + threadIdx.x;
    if (i < N_NODES) g_counts[i] = 0;
}

__global__ void hist_kernel(const int* __restrict__ rows, int nE) {
    int i = blockIdx.x * blockDim.x + threadIdx.x;
    int base = i * 4;
    if (base + 4 <= nE) {
        int4 r4 = *(const int4*)(rows + base);
        atomicAdd(&g_counts[r4.x], 1);
        atomicAdd(&g_counts[r4.y], 1);
        atomicAdd(&g_counts[r4.z], 1);
        atomicAdd(&g_counts[r4.w], 1);
    } else {
        for (int e = base; e < nE; e++) atomicAdd(&g_counts[rows[e]], 1);
    }
}

// Phase A: per-block sum of 1024 counts (coalesced).
__global__ __launch_bounds__(SCAN_BLK) void scan_partial_kernel() {
    __shared__ int wsum[32];
    int tid = threadIdx.x;
    int i = blockIdx.x * SCAN_BLK + tid;
    int v = (i < N_NODES) ? g_counts[i] : 0;

    int s = v;
#pragma unroll
    for (int off = 16; off; off >>= 1) s += __shfl_down_sync(0xffffffffu, s, off);
    if ((tid & 31) == 0) wsum[tid >> 5] = s;
    __syncthreads();
    if (tid < 32) {
        int t = wsum[tid];
#pragma unroll
        for (int off = 16; off; off >>= 1) t += __shfl_down_sync(0xffffffffu, t, off);
        if (tid == 0) g_partials[blockIdx.x] = t;
    }
}

// Phase B: single small block scans the 98 partials (exclusive), writes total.
__global__ __launch_bounds__(128) void scan_partials_scan_kernel() {
    __shared__ int sp[N_SCAN_BLOCKS];
    int tid = threadIdx.x;
    if (tid < N_SCAN_BLOCKS) sp[tid] = g_partials[tid];
    __syncthreads();
    if (tid == 0) {
        int run = 0;
        for (int b = 0; b < N_SCAN_BLOCKS; b++) {
            int c = sp[b];
            sp[b] = run;
            run += c;
        }
        g_row_ptr[N_NODES] = run;
    }
    __syncthreads();
    if (tid < N_SCAN_BLOCKS) g_partials[tid] = sp[tid];
}

// Phase C: block-level exclusive scan + block offset -> row_ptr / cursor.
__global__ __launch_bounds__(SCAN_BLK) void scan_apply_kernel() {
    __shared__ int wsum[32];
    int tid = threadIdx.x;
    int lane = tid & 31;
    int wid = tid >> 5;
    int i = blockIdx.x * SCAN_BLK + tid;
    int v = (i < N_NODES) ? g_counts[i] : 0;

    int inc = v;
#pragma unroll
    for (int off = 1; off < 32; off <<= 1) {
        int n = __shfl_up_sync(0xffffffffu, inc, off);
        if (lane >= off) inc += n;
    }
    if (lane == 31) wsum[wid] = inc;
    __syncthreads();
    if (wid == 0) {
        int t = (lane < 32) ? wsum[lane] : 0;
#pragma unroll
        for (int off = 1; off < 32; off <<= 1) {
            int n = __shfl_up_sync(0xffffffffu, t, off);
            if (lane >= off) t += n;
        }
        wsum[lane] = t;
    }
    __syncthreads();

    int warp_off = (wid == 0) ? 0 : wsum[wid - 1];
    int excl = inc - v + warp_off + g_partials[blockIdx.x];
    if (i < N_NODES) {
        g_row_ptr[i] = excl;
        g_cursor[i]  = excl;
    }
}

__global__ void scatter_kernel(const int* __restrict__ rows,
                               const int* __restrict__ cols,
                               const float* __restrict__ vals,
                               int nE) {
    int i = blockIdx.x * blockDim.x + threadIdx.x;
    int base = i * 4;
    if (base + 4 <= nE) {
        int4   r4 = *(const int4*)(rows + base);
        int4   c4 = *(const int4*)(cols + base);
        float4 v4 = *(const float4*)(vals + base);
        int p0 = atomicAdd(&g_cursor[r4.x], 1);
        int p1 = atomicAdd(&g_cursor[r4.y], 1);
        int p2 = atomicAdd(&g_cursor[r4.z], 1);
        int p3 = atomicAdd(&g_cursor[r4.w], 1);
        g_edges[p0] = ((long long)__float_as_int(v4.x) << 32) | (unsigned int)c4.x;
        g_edges[p1] = ((long long)__float_as_int(v4.y) << 32) | (unsigned int)c4.y;
        g_edges[p2] = ((long long)__float_as_int(v4.z) << 32) | (unsigned int)c4.z;
        g_edges[p3] = ((long long)__float_as_int(v4.w) << 32) | (unsigned int)c4.w;
    } else {
        for (int e = base; e < nE; e++) {
            int r = rows[e];
            int pos = atomicAdd(&g_cursor[r], 1);
            g_edges[pos] = ((long long)__float_as_int(vals[e]) << 32) | (unsigned int)cols[e];
        }
    }
}

// ---------------------------------------------------------------------------
// GEMM1 (fp16 tensor, m16n8k16, double-buffered): h0 = x @ W1.
// Register-staged prefetch of chunk k+1 overlaps MMA of chunk k.
// One __syncthreads per chunk.
// ---------------------------------------------------------------------------
__global__ __launch_bounds__(256) void gemm1_fp16_kernel(const float* __restrict__ X,
                                                         const float* __restrict__ W1) {
    __shared__ __half As[2][128][40];   // As[buf][m][k]
    __shared__ __half Bt[2][128][40];   // Bt[buf][n][k]

    const int tid  = threadIdx.x;
    const int lane = tid & 31;
    const int warp = tid >> 5;
    const int warpM = warp >> 2;
    const int warpN = warp & 3;
    const int gid = lane >> 2;
    const int tig = lane & 3;
    const int m0 = blockIdx.x * 128;

    // Per-thread load indices (4 items each for A and B fills)
    int a_r[4], a_c4[4], b_n[4], b_k4[4];
#pragma unroll
    for (int q = 0; q < 4; q++) {
        int ia = tid + q * 256;          // 0..1023
        a_r[q]  = ia >> 3;
        a_c4[q] = (ia & 7) * 4;
        b_n[q]  = ia & 127;
        b_k4[q] = (ia >> 7) * 4;
    }

    float4 a_stage[4];
    float  b_stage[4][4];

    auto load_regs = [&](int kc) {
#pragma unroll
        for (int q = 0; q < 4; q++) {
            int gm = m0 + a_r[q];
            float4 v = make_float4(0.f, 0.f, 0.f, 0.f);
            if (gm < N_NODES)
                v = *(const float4*)(X + (size_t)gm * IN_F + kc + a_c4[q]);
            a_stage[q] = v;
        }
#pragma unroll
        for (int q = 0; q < 4; q++) {
            int n = b_n[q];
            int k4 = b_k4[q];
            b_stage[q][0] = W1[(size_t)(kc + k4 + 0) * HID_F + n];
            b_stage[q][1] = W1[(size_t)(kc + k4 + 1) * HID_F + n];
            b_stage[q][2] = W1[(size_t)(kc + k4 + 2) * HID_F + n];
            b_stage[q][3] = W1[(size_t)(kc + k4 + 3) * HID_F + n];
        }
    };

    auto store_smem = [&](int buf) {
#pragma unroll
        for (int q = 0; q < 4; q++) {
            __half2 h0 = __floats2half2_rn(a_stage[q].x, a_stage[q].y);
            __half2 h1 = __floats2half2_rn(a_stage[q].z, a_stage[q].w);
            uint2 pk;
            pk.x = *(unsigned*)&h0;
            pk.y = *(unsigned*)&h1;
            *(uint2*)&As[buf][a_r[q]][a_c4[q]] = pk;
        }
#pragma unroll
        for (int q = 0; q < 4; q++) {
            __half2 h0 = __floats2half2_rn(b_stage[q][0], b_stage[q][1]);
            __half2 h1 = __floats2half2_rn(b_stage[q][2], b_stage[q][3]);
            uint2 pk;
            pk.x = *(unsigned*)&h0;
            pk.y = *(unsigned*)&h1;
            *(uint2*)&Bt[buf][b_n[q]][b_k4[q]] = pk;
        }
    };

    float acc[4][4][4];
#pragma unroll
    for (int a = 0; a < 4; a++)
#pragma unroll
        for (int b = 0; b < 4; b++)
#pragma unroll
            for (int c = 0; c < 4; c++) acc[a][b][c] = 0.f;

    // Prologue: chunk 0 into buf 0
    load_regs(0);
    store_smem(0);
    __syncthreads();

    const int NCHUNK = IN_F / 32;   // 8
    for (int kc = 0; kc < NCHUNK; kc++) {
        int cur = kc & 1;
        if (kc + 1 < NCHUNK) load_regs((kc + 1) * 32);   // LDGs overlap MMA

#pragma unroll
        for (int ks = 0; ks < 2; ks++) {
            const int k = ks * 16;
            unsigned afrag[4][4];
#pragma unroll
            for (int mt = 0; mt < 4; mt++) {
                int rm = warpM * 64 + mt * 16;
                afrag[mt][0] = *(unsigned*)&As[cur][rm + gid][k + 2 * tig];
                afrag[mt][1] = *(unsigned*)&As[cur][rm + gid + 8][k + 2 * tig];
                afrag[mt][2] = *(unsigned*)&As[cur][rm + gid][k + 2 * tig + 8];
                afrag[mt][3] = *(unsigned*)&As[cur][rm + gid + 8][k + 2 * tig + 8];
            }
            unsigned bfrag[4][2];
#pragma unroll
            for (int nt = 0; nt < 4; nt++) {
                int nb = warpN * 32 + nt * 8 + gid;
                bfrag[nt][0] = *(unsigned*)&Bt[cur][nb][k + 2 * tig];
                bfrag[nt][1] = *(unsigned*)&Bt[cur][nb][k + 2 * tig + 8];
            }
#pragma unroll
            for (int mt = 0; mt < 4; mt++)
#pragma unroll
                for (int nt = 0; nt < 4; nt++) {
                    asm volatile(
                        "mma.sync.aligned.m16n8k16.row.col.f32.f16.f16.f32 "
                        "{%0,%1,%2,%3}, {%4,%5,%6,%7}, {%8,%9}, {%0,%1,%2,%3};"
                        : "+f"(acc[mt][nt][0]), "+f"(acc[mt][nt][1]),
                          "+f"(acc[mt][nt][2]), "+f"(acc[mt][nt][3])
                        : "r"(afrag[mt][0]), "r"(afrag[mt][1]),
                          "r"(afrag[mt][2]), "r"(afrag[mt][3]),
                          "r"(bfrag[nt][0]), "r"(bfrag[nt][1]));
                }
        }

        if (kc + 1 < NCHUNK) {
            store_smem(cur ^ 1);
            __syncthreads();
        }
    }

#pragma unroll
    for (int mt = 0; mt < 4; mt++) {
#pragma unroll
        for (int nt = 0; nt < 4; nt++) {
            int col = warpN * 32 + nt * 8 + 2 * tig;
            int r0 = m0 + warpM * 64 + mt * 16 + gid;
            int r1 = r0 + 8;
            if (r0 < N_NODES) {
                __half2 h = __floats2half2_rn(acc[mt][nt][0], acc[mt][nt][1]);
                *(__half2*)(g_h0h + (size_t)r0 * HID_F + col) = h;
            }
            if (r1 < N_NODES) {
                __half2 h = __floats2half2_rn(acc[mt][nt][2], acc[mt][nt][3]);
                *(__half2*)(g_h0h + (size_t)r1 * HID_F + col) = h;
            }
        }
    }
}

// ---------------------------------------------------------------------------
// SpMM1 gather (F=128, fp16 payload) — R6/R8 winning form; fp16 output.
// ---------------------------------------------------------------------------
__device__ __forceinline__ void fma_h4(float4& acc, uint2 m, float v) {
    float2 f0 = __half22float2(*(__half2*)&m.x);
    float2 f1 = __half22float2(*(__half2*)&m.y);
    acc.x = fmaf(f0.x, v, acc.x);
    acc.y = fmaf(f0.y, v, acc.y);
    acc.z = fmaf(f1.x, v, acc.z);
    acc.w = fmaf(f1.y, v, acc.w);
}

__global__ __launch_bounds__(256) void spmm128_csr_kernel() {
    int row = blockIdx.x * 8 + (threadIdx.x >> 5);
    if (row >= N_NODES) return;
    int lane = threadIdx.x & 31;

    int e  = __ldg(&g_row_ptr[row]);
    int e1 = __ldg(&g_row_ptr[row + 1]);

    float4 acc = make_float4(0.f, 0.f, 0.f, 0.f);

    for (; e + 4 <= e1; e += 4) {
        long long p0 = __ldg(&g_edges[e + 0]);
        long long p1 = __ldg(&g_edges[e + 1]);
        long long p2 = __ldg(&g_edges[e + 2]);
        long long p3 = __ldg(&g_edges[e + 3]);
        uint2 m0 = *((const uint2*)(g_h0h + (size_t)(unsigned int)(p0 & 0xffffffffLL) * HID_F) + lane);
        uint2 m1 = *((const uint2*)(g_h0h + (size_t)(unsigned int)(p1 & 0xffffffffLL) * HID_F) + lane);
        uint2 m2 = *((const uint2*)(g_h0h + (size_t)(unsigned int)(p2 & 0xffffffffLL) * HID_F) + lane);
        uint2 m3 = *((const uint2*)(g_h0h + (size_t)(unsigned int)(p3 & 0xffffffffLL) * HID_F) + lane);
        fma_h4(acc, m0, __int_as_float((int)(p0 >> 32)));
        fma_h4(acc, m1, __int_as_float((int)(p1 >> 32)));
        fma_h4(acc, m2, __int_as_float((int)(p2 >> 32)));
        fma_h4(acc, m3, __int_as_float((int)(p3 >> 32)));
    }
    for (; e < e1; e++) {
        long long pk = __ldg(&g_edges[e]);
        int c  = (int)(unsigned int)(pk & 0xffffffffLL);
        uint2 m = *((const uint2*)(g_h0h + (size_t)c * HID_F) + lane);
        fma_h4(acc, m, __int_as_float((int)(pk >> 32)));
    }

    __half2 o0 = __floats2half2_rn(acc.x, acc.y);
    __half2 o1 = __floats2half2_rn(acc.z, acc.w);
    uint2 pk;
    pk.x = *(unsigned*)&o0;
    pk.y = *(unsigned*)&o1;
    *((uint2*)(g_h1h + (size_t)row * HID_F) + lane) = pk;
}

// ---------------------------------------------------------------------------
// GEMM2: g_h2h[M,32] = fp16( relu(g_h1h)[M,128] @ W2[128,32] ), fp16 input.
// ---------------------------------------------------------------------------
__global__ __launch_bounds__(256) void gemm2_kernel(const float* __restrict__ W2) {
    __shared__ float Ws[HID_F * OUT_F];
    for (int i = threadIdx.x; i < HID_F * OUT_F; i += 256) Ws[i] = W2[i];
    __syncthreads();

    int r = blockIdx.x * 256 + threadIdx.x;
    if (r >= N_NODES) return;

    float acc[OUT_F];
#pragma unroll
    for (int n = 0; n < OUT_F; n++) acc[n] = 0.f;

    const uint2* hp = (const uint2*)(g_h1h + (size_t)r * HID_F);
#pragma unroll 4
    for (int k4 = 0; k4 < HID_F / 4; k4++) {
        uint2 u = hp[k4];
        float2 f0 = __half22float2(*(__half2*)&u.x);
        float2 f1 = __half22float2(*(__half2*)&u.y);
        float hh[4];
        hh[0] = fmaxf(f0.x, 0.f);
        hh[1] = fmaxf(f0.y, 0.f);
        hh[2] = fmaxf(f1.x, 0.f);
        hh[3] = fmaxf(f1.y, 0.f);
        int k = k4 * 4;
#pragma unroll
        for (int dk = 0; dk < 4; dk++) {
#pragma unroll
            for (int n = 0; n < OUT_F; n += 4) {
                float4 w = *(const float4*)&Ws[(k + dk) * OUT_F + n];
                acc[n + 0] = fmaf(hh[dk], w.x, acc[n + 0]);
                acc[n + 1] = fmaf(hh[dk], w.y, acc[n + 1]);
                acc[n + 2] = fmaf(hh[dk], w.z, acc[n + 2]);
                acc[n + 3] = fmaf(hh[dk], w.w, acc[n + 3]);
            }
        }
    }

    __half2 hb[OUT_F / 2];
#pragma unroll
    for (int n = 0; n < OUT_F / 2; n++)
        hb[n] = __floats2half2_rn(acc[2 * n], acc[2 * n + 1]);
    uint4* op = (uint4*)(g_h2h + (size_t)r * OUT_F);
#pragma unroll
    for (int q = 0; q < 4; q++)
        op[q] = ((uint4*)hb)[q];
}

// ---------------------------------------------------------------------------
// SpMM2 gather (F=32, fp16 payload) — R8 form.
// ---------------------------------------------------------------------------
__global__ __launch_bounds__(256) void spmm32_csr_kernel(float* __restrict__ out) {
    int row = blockIdx.x * 32 + (threadIdx.x >> 3);
    if (row >= N_NODES) return;
    int lane = threadIdx.x & 7;

    int e  = __ldg(&g_row_ptr[row]);
    int e1 = __ldg(&g_row_ptr[row + 1]);

    float4 acc = make_float4(0.f, 0.f, 0.f, 0.f);

    for (; e + 4 <= e1; e += 4) {
        long long p0 = __ldg(&g_edges[e + 0]);
        long long p1 = __ldg(&g_edges[e + 1]);
        long long p2 = __ldg(&g_edges[e + 2]);
        long long p3 = __ldg(&g_edges[e + 3]);
        uint2 m0 = *((const uint2*)(g_h2h + (size_t)(unsigned int)(p0 & 0xffffffffLL) * OUT_F) + lane);
        uint2 m1 = *((const uint2*)(g_h2h + (size_t)(unsigned int)(p1 & 0xffffffffLL) * OUT_F) + lane);
        uint2 m2 = *((const uint2*)(g_h2h + (size_t)(unsigned int)(p2 & 0xffffffffLL) * OUT_F) + lane);
        uint2 m3 = *((const uint2*)(g_h2h + (size_t)(unsigned int)(p3 & 0xffffffffLL) * OUT_F) + lane);
        fma_h4(acc, m0, __int_as_float((int)(p0 >> 32)));
        fma_h4(acc, m1, __int_as_float((int)(p1 >> 32)));
        fma_h4(acc, m2, __int_as_float((int)(p2 >> 32)));
        fma_h4(acc, m3, __int_as_float((int)(p3 >> 32)));
    }
    for (; e < e1; e++) {
        long long pk = __ldg(&g_edges[e]);
        int c  = (int)(unsigned int)(pk & 0xffffffffLL);
        uint2 m = *((const uint2*)(g_h2h + (size_t)c * OUT_F) + lane);
        fma_h4(acc, m, __int_as_float((int)(pk >> 32)));
    }
    *((float4*)(out + (size_t)row * OUT_F) + lane) = acc;
}

// ---------------------------------------------------------------------------
// Launch. Fork-join: CSR build chain on a side stream concurrent with GEMM1.
// Inputs (metadata order): x, adj_rows, adj_cols, adj_vals, W1, W2
// ---------------------------------------------------------------------------
extern "C" void kernel_launch(void* const* d_in, const int* in_sizes, int n_in,
                              void* d_out, int out_size) {
    const float* x    = (const float*)d_in[0];
    const int*   rows = (const int*)d_in[1];
    const int*   cols = (const int*)d_in[2];
    const float* vals = (const float*)d_in[3];
    const float* W1   = (const float*)d_in[4];
    const float* W2   = (const float*)d_in[5];
    float* out = (float*)d_out;

    const int nE = in_sizes[1];

    static cudaStream_t s_side = nullptr;
    static cudaEvent_t  e_fork = nullptr;
    static cudaEvent_t  e_join = nullptr;
    if (s_side == nullptr) {
        cudaStreamCreateWithFlags(&s_side, cudaStreamNonBlocking);
        cudaEventCreateWithFlags(&e_fork, cudaEventDisableTiming);
        cudaEventCreateWithFlags(&e_join, cudaEventDisableTiming);
    }

    cudaEventRecord(e_fork, 0);
    cudaStreamWaitEvent(s_side, e_fork, 0);

    // --- Side stream: CSR build chain ---
    zero_counts_kernel<<<(N_NODES + 255) / 256, 256, 0, s_side>>>();
    hist_kernel<<<(nE / 4 + 255) / 256, 256, 0, s_side>>>(rows, nE);
    scan_partial_kernel<<<N_SCAN_BLOCKS, SCAN_BLK, 0, s_side>>>();
    scan_partials_scan_kernel<<<1, 128, 0, s_side>>>();
    scan_apply_kernel<<<N_SCAN_BLOCKS, SCAN_BLK, 0, s_side>>>();
    scatter_kernel<<<(nE / 4 + 255) / 256, 256, 0, s_side>>>(rows, cols, vals, nE);
    cudaEventRecord(e_join, s_side);

    // --- Main stream (concurrent): GEMM1 (double-buffered) ---
    gemm1_fp16_kernel<<<(N_NODES + 127) / 128, 256>>>(x, W1);

    cudaStreamWaitEvent(0, e_join, 0);

    // SpMM1: h1 = A_hat @ h0  (fp16 gather, fp32 accum, fp16 store)
    spmm128_csr_kernel<<<(N_NODES + 7) / 8, 256>>>();

    // GEMM2: h2 = relu(h1) @ W2 (fp16 in/out)
    gemm2_kernel<<<(N_NODES + 255) / 256, 256>>>(W2);

    // SpMM2: out = A_hat @ h2  (fp16 gather, fp32 accum)
    spmm32_csr_kernel<<<(N_NODES + 31) / 32, 256>>>(out);
}

// round 13
// speedup vs baseline: 1.0788x; 1.0788x over previous
#include <cuda_runtime.h>
#include <cuda_fp16.h>

#define N_NODES 100000
#define N_EDGES_MAX 1600000
#define IN_F    256
#define HID_F   128
#define OUT_F   32

#define SCAN_BLK 1024
#define N_SCAN_BLOCKS ((N_NODES + SCAN_BLK - 1) / SCAN_BLK)   // 98

// Scratch: __device__ globals (no allocation allowed anywhere).
__device__ __half g_h0h[(size_t)N_NODES * HID_F];  // x @ W1   (fp16 payload)
__device__ __half g_h1h[(size_t)N_NODES * HID_F];  // spmm1 out (fp16 payload)
__device__ __half g_h2h[(size_t)N_NODES * OUT_F];  // relu(h1) @ W2 (fp16)

// CSR scratch
__device__ int       g_counts[N_NODES];
__device__ int       g_row_ptr[N_NODES + 1];
__device__ int       g_cursor[N_NODES];
__device__ int       g_partials[N_SCAN_BLOCKS];
__device__ long long g_edges[N_EDGES_MAX];   // packed: low32=col, high32=val bits

// ---------------------------------------------------------------------------
// CSR build
// ---------------------------------------------------------------------------
__global__ void zero_counts_kernel() {
    int i = blockIdx.x * blockDim.x + threadIdx.x;
    if (i < N_NODES) g_counts[i] = 0;
}

__global__ void hist_kernel(const int* __restrict__ rows, int nE) {
    int i = blockIdx.x * blockDim.x + threadIdx.x;
    int base = i * 4;
    if (base + 4 <= nE) {
        int4 r4 = *(const int4*)(rows + base);
        atomicAdd(&g_counts[r4.x], 1);
        atomicAdd(&g_counts[r4.y], 1);
        atomicAdd(&g_counts[r4.z], 1);
        atomicAdd(&g_counts[r4.w], 1);
    } else {
        for (int e = base; e < nE; e++) atomicAdd(&g_counts[rows[e]], 1);
    }
}

// Phase A: per-block sum of 1024 counts (coalesced).
__global__ __launch_bounds__(SCAN_BLK) void scan_partial_kernel() {
    __shared__ int wsum[32];
    int tid = threadIdx.x;
    int i = blockIdx.x * SCAN_BLK + tid;
    int v = (i < N_NODES) ? g_counts[i] : 0;

    int s = v;
#pragma unroll
    for (int off = 16; off; off >>= 1) s += __shfl_down_sync(0xffffffffu, s, off);
    if ((tid & 31) == 0) wsum[tid >> 5] = s;
    __syncthreads();
    if (tid < 32) {
        int t = wsum[tid];
#pragma unroll
        for (int off = 16; off; off >>= 1) t += __shfl_down_sync(0xffffffffu, t, off);
        if (tid == 0) g_partials[blockIdx.x] = t;
    }
}

// Phase B: single small block scans the 98 partials (exclusive), writes total.
__global__ __launch_bounds__(128) void scan_partials_scan_kernel() {
    __shared__ int sp[N_SCAN_BLOCKS];
    int tid = threadIdx.x;
    if (tid < N_SCAN_BLOCKS) sp[tid] = g_partials[tid];
    __syncthreads();
    if (tid == 0) {
        int run = 0;
        for (int b = 0; b < N_SCAN_BLOCKS; b++) {
            int c = sp[b];
            sp[b] = run;
            run += c;
        }
        g_row_ptr[N_NODES] = run;
    }
    __syncthreads();
    if (tid < N_SCAN_BLOCKS) g_partials[tid] = sp[tid];
}

// Phase C: block-level exclusive scan + block offset -> row_ptr / cursor.
__global__ __launch_bounds__(SCAN_BLK) void scan_apply_kernel() {
    __shared__ int wsum[32];
    int tid = threadIdx.x;
    int lane = tid & 31;
    int wid = tid >> 5;
    int i = blockIdx.x * SCAN_BLK + tid;
    int v = (i < N_NODES) ? g_counts[i] : 0;

    int inc = v;
#pragma unroll
    for (int off = 1; off < 32; off <<= 1) {
        int n = __shfl_up_sync(0xffffffffu, inc, off);
        if (lane >= off) inc += n;
    }
    if (lane == 31) wsum[wid] = inc;
    __syncthreads();
    if (wid == 0) {
        int t = (lane < 32) ? wsum[lane] : 0;
#pragma unroll
        for (int off = 1; off < 32; off <<= 1) {
            int n = __shfl_up_sync(0xffffffffu, t, off);
            if (lane >= off) t += n;
        }
        wsum[lane] = t;
    }
    __syncthreads();

    int warp_off = (wid == 0) ? 0 : wsum[wid - 1];
    int excl = inc - v + warp_off + g_partials[blockIdx.x];
    if (i < N_NODES) {
        g_row_ptr[i] = excl;
        g_cursor[i]  = excl;
    }
}

__global__ void scatter_kernel(const int* __restrict__ rows,
                               const int* __restrict__ cols,
                               const float* __restrict__ vals,
                               int nE) {
    int i = blockIdx.x * blockDim.x + threadIdx.x;
    int base = i * 4;
    if (base + 4 <= nE) {
        int4   r4 = *(const int4*)(rows + base);
        int4   c4 = *(const int4*)(cols + base);
        float4 v4 = *(const float4*)(vals + base);
        int p0 = atomicAdd(&g_cursor[r4.x], 1);
        int p1 = atomicAdd(&g_cursor[r4.y], 1);
        int p2 = atomicAdd(&g_cursor[r4.z], 1);
        int p3 = atomicAdd(&g_cursor[r4.w], 1);
        g_edges[p0] = ((long long)__float_as_int(v4.x) << 32) | (unsigned int)c4.x;
        g_edges[p1] = ((long long)__float_as_int(v4.y) << 32) | (unsigned int)c4.y;
        g_edges[p2] = ((long long)__float_as_int(v4.z) << 32) | (unsigned int)c4.z;
        g_edges[p3] = ((long long)__float_as_int(v4.w) << 32) | (unsigned int)c4.w;
    } else {
        for (int e = base; e < nE; e++) {
            int r = rows[e];
            int pos = atomicAdd(&g_cursor[r], 1);
            g_edges[pos] = ((long long)__float_as_int(vals[e]) << 32) | (unsigned int)cols[e];
        }
    }
}

// ---------------------------------------------------------------------------
// GEMM1 (fp16 tensor, m16n8k16): h0[M,128] = x[M,256] @ W1[256,128].
// R8/R11 proven single-buffer form.
// ---------------------------------------------------------------------------
__global__ __launch_bounds__(256) void gemm1_fp16_kernel(const float* __restrict__ X,
                                                         const float* __restrict__ W1) {
    __shared__ __half As[128][40];   // As[m][k]
    __shared__ __half Bt[128][40];   // Bt[n][k]

    const int tid  = threadIdx.x;
    const int lane = tid & 31;
    const int warp = tid >> 5;
    const int warpM = warp >> 2;
    const int warpN = warp & 3;
    const int gid = lane >> 2;
    const int tig = lane & 3;
    const int m0 = blockIdx.x * 128;

    float acc[4][4][4];
#pragma unroll
    for (int a = 0; a < 4; a++)
#pragma unroll
        for (int b = 0; b < 4; b++)
#pragma unroll
            for (int c = 0; c < 4; c++) acc[a][b][c] = 0.f;

    for (int kc = 0; kc < IN_F; kc += 32) {
#pragma unroll
        for (int i = tid; i < 1024; i += 256) {
            int r  = i >> 3;
            int c4 = (i & 7) * 4;
            int gm = m0 + r;
            float4 v = make_float4(0.f, 0.f, 0.f, 0.f);
            if (gm < N_NODES)
                v = *(const float4*)(X + (size_t)gm * IN_F + kc + c4);
            __half2 h0 = __floats2half2_rn(v.x, v.y);
            __half2 h1 = __floats2half2_rn(v.z, v.w);
            uint2 pk;
            pk.x = *(unsigned*)&h0;
            pk.y = *(unsigned*)&h1;
            *(uint2*)&As[r][c4] = pk;
        }
#pragma unroll
        for (int i = tid; i < 1024; i += 256) {
            int n  = i & 127;
            int k4 = (i >> 7) * 4;
            float f0 = W1[(size_t)(kc + k4 + 0) * HID_F + n];
            float f1 = W1[(size_t)(kc + k4 + 1) * HID_F + n];
            float f2 = W1[(size_t)(kc + k4 + 2) * HID_F + n];
            float f3 = W1[(size_t)(kc + k4 + 3) * HID_F + n];
            __half2 h0 = __floats2half2_rn(f0, f1);
            __half2 h1 = __floats2half2_rn(f2, f3);
            uint2 pk;
            pk.x = *(unsigned*)&h0;
            pk.y = *(unsigned*)&h1;
            *(uint2*)&Bt[n][k4] = pk;
        }
        __syncthreads();

#pragma unroll
        for (int ks = 0; ks < 2; ks++) {
            const int k = ks * 16;
            unsigned afrag[4][4];
#pragma unroll
            for (int mt = 0; mt < 4; mt++) {
                int rm = warpM * 64 + mt * 16;
                afrag[mt][0] = *(unsigned*)&As[rm + gid][k + 2 * tig];
                afrag[mt][1] = *(unsigned*)&As[rm + gid + 8][k + 2 * tig];
                afrag[mt][2] = *(unsigned*)&As[rm + gid][k + 2 * tig + 8];
                afrag[mt][3] = *(unsigned*)&As[rm + gid + 8][k + 2 * tig + 8];
            }
            unsigned bfrag[4][2];
#pragma unroll
            for (int nt = 0; nt < 4; nt++) {
                int nb = warpN * 32 + nt * 8 + gid;
                bfrag[nt][0] = *(unsigned*)&Bt[nb][k + 2 * tig];
                bfrag[nt][1] = *(unsigned*)&Bt[nb][k + 2 * tig + 8];
            }
#pragma unroll
            for (int mt = 0; mt < 4; mt++)
#pragma unroll
                for (int nt = 0; nt < 4; nt++) {
                    asm volatile(
                        "mma.sync.aligned.m16n8k16.row.col.f32.f16.f16.f32 "
                        "{%0,%1,%2,%3}, {%4,%5,%6,%7}, {%8,%9}, {%0,%1,%2,%3};"
                        : "+f"(acc[mt][nt][0]), "+f"(acc[mt][nt][1]),
                          "+f"(acc[mt][nt][2]), "+f"(acc[mt][nt][3])
                        : "r"(afrag[mt][0]), "r"(afrag[mt][1]),
                          "r"(afrag[mt][2]), "r"(afrag[mt][3]),
                          "r"(bfrag[nt][0]), "r"(bfrag[nt][1]));
                }
        }
        __syncthreads();
    }

#pragma unroll
    for (int mt = 0; mt < 4; mt++) {
#pragma unroll
        for (int nt = 0; nt < 4; nt++) {
            int col = warpN * 32 + nt * 8 + 2 * tig;
            int r0 = m0 + warpM * 64 + mt * 16 + gid;
            int r1 = r0 + 8;
            if (r0 < N_NODES) {
                __half2 h = __floats2half2_rn(acc[mt][nt][0], acc[mt][nt][1]);
                *(__half2*)(g_h0h + (size_t)r0 * HID_F + col) = h;
            }
            if (r1 < N_NODES) {
                __half2 h = __floats2half2_rn(acc[mt][nt][2], acc[mt][nt][3]);
                *(__half2*)(g_h0h + (size_t)r1 * HID_F + col) = h;
            }
        }
    }
}

// ---------------------------------------------------------------------------
// SpMM1 gather (F=128, fp16 payload) — R6/R8 winning form; fp16 output.
// ---------------------------------------------------------------------------
__device__ __forceinline__ void fma_h4(float4& acc, uint2 m, float v) {
    float2 f0 = __half22float2(*(__half2*)&m.x);
    float2 f1 = __half22float2(*(__half2*)&m.y);
    acc.x = fmaf(f0.x, v, acc.x);
    acc.y = fmaf(f0.y, v, acc.y);
    acc.z = fmaf(f1.x, v, acc.z);
    acc.w = fmaf(f1.y, v, acc.w);
}

__global__ __launch_bounds__(256) void spmm128_csr_kernel() {
    int row = blockIdx.x * 8 + (threadIdx.x >> 5);
    if (row >= N_NODES) return;
    int lane = threadIdx.x & 31;

    int e  = __ldg(&g_row_ptr[row]);
    int e1 = __ldg(&g_row_ptr[row + 1]);

    float4 acc = make_float4(0.f, 0.f, 0.f, 0.f);

    for (; e + 4 <= e1; e += 4) {
        long long p0 = __ldg(&g_edges[e + 0]);
        long long p1 = __ldg(&g_edges[e + 1]);
        long long p2 = __ldg(&g_edges[e + 2]);
        long long p3 = __ldg(&g_edges[e + 3]);
        uint2 m0 = *((const uint2*)(g_h0h + (size_t)(unsigned int)(p0 & 0xffffffffLL) * HID_F) + lane);
        uint2 m1 = *((const uint2*)(g_h0h + (size_t)(unsigned int)(p1 & 0xffffffffLL) * HID_F) + lane);
        uint2 m2 = *((const uint2*)(g_h0h + (size_t)(unsigned int)(p2 & 0xffffffffLL) * HID_F) + lane);
        uint2 m3 = *((const uint2*)(g_h0h + (size_t)(unsigned int)(p3 & 0xffffffffLL) * HID_F) + lane);
        fma_h4(acc, m0, __int_as_float((int)(p0 >> 32)));
        fma_h4(acc, m1, __int_as_float((int)(p1 >> 32)));
        fma_h4(acc, m2, __int_as_float((int)(p2 >> 32)));
        fma_h4(acc, m3, __int_as_float((int)(p3 >> 32)));
    }
    for (; e < e1; e++) {
        long long pk = __ldg(&g_edges[e]);
        int c  = (int)(unsigned int)(pk & 0xffffffffLL);
        uint2 m = *((const uint2*)(g_h0h + (size_t)c * HID_F) + lane);
        fma_h4(acc, m, __int_as_float((int)(pk >> 32)));
    }

    __half2 o0 = __floats2half2_rn(acc.x, acc.y);
    __half2 o1 = __floats2half2_rn(acc.z, acc.w);
    uint2 pk;
    pk.x = *(unsigned*)&o0;
    pk.y = *(unsigned*)&o1;
    *((uint2*)(g_h1h + (size_t)row * HID_F) + lane) = pk;
}

// ---------------------------------------------------------------------------
// GEMM2: g_h2h[M,32] = fp16( relu(g_h1h)[M,128] @ W2[128,32] ), fp16 input.
// ---------------------------------------------------------------------------
__global__ __launch_bounds__(256) void gemm2_kernel(const float* __restrict__ W2) {
    __shared__ float Ws[HID_F * OUT_F];
    for (int i = threadIdx.x; i < HID_F * OUT_F; i += 256) Ws[i] = W2[i];
    __syncthreads();

    int r = blockIdx.x * 256 + threadIdx.x;
    if (r >= N_NODES) return;

    float acc[OUT_F];
#pragma unroll
    for (int n = 0; n < OUT_F; n++) acc[n] = 0.f;

    const uint2* hp = (const uint2*)(g_h1h + (size_t)r * HID_F);
#pragma unroll 4
    for (int k4 = 0; k4 < HID_F / 4; k4++) {
        uint2 u = hp[k4];
        float2 f0 = __half22float2(*(__half2*)&u.x);
        float2 f1 = __half22float2(*(__half2*)&u.y);
        float hh[4];
        hh[0] = fmaxf(f0.x, 0.f);
        hh[1] = fmaxf(f0.y, 0.f);
        hh[2] = fmaxf(f1.x, 0.f);
        hh[3] = fmaxf(f1.y, 0.f);
        int k = k4 * 4;
#pragma unroll
        for (int dk = 0; dk < 4; dk++) {
#pragma unroll
            for (int n = 0; n < OUT_F; n += 4) {
                float4 w = *(const float4*)&Ws[(k + dk) * OUT_F + n];
                acc[n + 0] = fmaf(hh[dk], w.x, acc[n + 0]);
                acc[n + 1] = fmaf(hh[dk], w.y, acc[n + 1]);
                acc[n + 2] = fmaf(hh[dk], w.z, acc[n + 2]);
                acc[n + 3] = fmaf(hh[dk], w.w, acc[n + 3]);
            }
        }
    }

    __half2 hb[OUT_F / 2];
#pragma unroll
    for (int n = 0; n < OUT_F / 2; n++)
        hb[n] = __floats2half2_rn(acc[2 * n], acc[2 * n + 1]);
    uint4* op = (uint4*)(g_h2h + (size_t)r * OUT_F);
#pragma unroll
    for (int q = 0; q < 4; q++)
        op[q] = ((uint4*)hb)[q];
}

// ---------------------------------------------------------------------------
// SpMM2 gather (F=32, fp16 payload) — R8 form.
// ---------------------------------------------------------------------------
__global__ __launch_bounds__(256) void spmm32_csr_kernel(float* __restrict__ out) {
    int row = blockIdx.x * 32 + (threadIdx.x >> 3);
    if (row >= N_NODES) return;
    int lane = threadIdx.x & 7;

    int e  = __ldg(&g_row_ptr[row]);
    int e1 = __ldg(&g_row_ptr[row + 1]);

    float4 acc = make_float4(0.f, 0.f, 0.f, 0.f);

    for (; e + 4 <= e1; e += 4) {
        long long p0 = __ldg(&g_edges[e + 0]);
        long long p1 = __ldg(&g_edges[e + 1]);
        long long p2 = __ldg(&g_edges[e + 2]);
        long long p3 = __ldg(&g_edges[e + 3]);
        uint2 m0 = *((const uint2*)(g_h2h + (size_t)(unsigned int)(p0 & 0xffffffffLL) * OUT_F) + lane);
        uint2 m1 = *((const uint2*)(g_h2h + (size_t)(unsigned int)(p1 & 0xffffffffLL) * OUT_F) + lane);
        uint2 m2 = *((const uint2*)(g_h2h + (size_t)(unsigned int)(p2 & 0xffffffffLL) * OUT_F) + lane);
        uint2 m3 = *((const uint2*)(g_h2h + (size_t)(unsigned int)(p3 & 0xffffffffLL) * OUT_F) + lane);
        fma_h4(acc, m0, __int_as_float((int)(p0 >> 32)));
        fma_h4(acc, m1, __int_as_float((int)(p1 >> 32)));
        fma_h4(acc, m2, __int_as_float((int)(p2 >> 32)));
        fma_h4(acc, m3, __int_as_float((int)(p3 >> 32)));
    }
    for (; e < e1; e++) {
        long long pk = __ldg(&g_edges[e]);
        int c  = (int)(unsigned int)(pk & 0xffffffffLL);
        uint2 m = *((const uint2*)(g_h2h + (size_t)c * OUT_F) + lane);
        fma_h4(acc, m, __int_as_float((int)(pk >> 32)));
    }
    *((float4*)(out + (size_t)row * OUT_F) + lane) = acc;
}

// ---------------------------------------------------------------------------
// Launch. Fork-join: CSR build chain on a side stream concurrent with GEMM1.
// Inputs (metadata order): x, adj_rows, adj_cols, adj_vals, W1, W2
// ---------------------------------------------------------------------------
extern "C" void kernel_launch(void* const* d_in, const int* in_sizes, int n_in,
                              void* d_out, int out_size) {
    const float* x    = (const float*)d_in[0];
    const int*   rows = (const int*)d_in[1];
    const int*   cols = (const int*)d_in[2];
    const float* vals = (const float*)d_in[3];
    const float* W1   = (const float*)d_in[4];
    const float* W2   = (const float*)d_in[5];
    float* out = (float*)d_out;

    const int nE = in_sizes[1];

    static cudaStream_t s_side = nullptr;
    static cudaEvent_t  e_fork = nullptr;
    static cudaEvent_t  e_join = nullptr;
    if (s_side == nullptr) {
        cudaStreamCreateWithFlags(&s_side, cudaStreamNonBlocking);
        cudaEventCreateWithFlags(&e_fork, cudaEventDisableTiming);
        cudaEventCreateWithFlags(&e_join, cudaEventDisableTiming);
    }

    cudaEventRecord(e_fork, 0);
    cudaStreamWaitEvent(s_side, e_fork, 0);

    // --- Side stream: CSR build chain ---
    zero_counts_kernel<<<(N_NODES + 255) / 256, 256, 0, s_side>>>();
    hist_kernel<<<(nE / 4 + 255) / 256, 256, 0, s_side>>>(rows, nE);
    scan_partial_kernel<<<N_SCAN_BLOCKS, SCAN_BLK, 0, s_side>>>();
    scan_partials_scan_kernel<<<1, 128, 0, s_side>>>();
    scan_apply_kernel<<<N_SCAN_BLOCKS, SCAN_BLK, 0, s_side>>>();
    scatter_kernel<<<(nE / 4 + 255) / 256, 256, 0, s_side>>>(rows, cols, vals, nE);
    cudaEventRecord(e_join, s_side);

    // --- Main stream (concurrent): GEMM1 ---
    gemm1_fp16_kernel<<<(N_NODES + 127) / 128, 256>>>(x, W1);

    cudaStreamWaitEvent(0, e_join, 0);

    // SpMM1: h1 = A_hat @ h0  (fp16 gather, fp32 accum, fp16 store)
    spmm128_csr_kernel<<<(N_NODES + 7) / 8, 256>>>();

    // GEMM2: h2 = relu(h1) @ W2 (fp16 in/out)
    gemm2_kernel<<<(N_NODES + 255) / 256, 256>>>(W2);

    // SpMM2: out = A_hat @ h2  (fp16 gather, fp32 accum)
    spmm32_csr_kernel<<<(N_NODES + 31) / 32, 256>>>(out);
}

// round 15
// speedup vs baseline: 1.1151x; 1.0337x over previous
#include <cuda_runtime.h>
#include <cuda_fp16.h>

#define N_NODES 100000
#define N_EDGES_MAX 1600000
#define IN_F    256
#define HID_F   128
#define OUT_F   32

#define SCAN_BLK 1024
#define N_SCAN_BLOCKS ((N_NODES + SCAN_BLK - 1) / SCAN_BLK)   // 98

// Scratch: __device__ globals (no allocation allowed anywhere).
__device__ __half g_h0h[(size_t)N_NODES * HID_F];  // x @ W1   (fp16 payload)
__device__ __half g_h1h[(size_t)N_NODES * HID_F];  // spmm1 out (fp16 payload)
__device__ __half g_h2h[(size_t)N_NODES * OUT_F];  // relu(h1) @ W2 (fp16)

// CSR scratch
__device__ int       g_counts[N_NODES];
__device__ int       g_row_ptr[N_NODES + 1];
__device__ int       g_cursor[N_NODES];
__device__ int       g_partials[N_SCAN_BLOCKS];
__device__ long long g_edges[N_EDGES_MAX];   // packed: low32=col, high32=val bits

// ---------------------------------------------------------------------------
// CSR build
// ---------------------------------------------------------------------------
__global__ void zero_counts_kernel() {
    int i = blockIdx.x * blockDim.x + threadIdx.x;
    if (i < N_NODES) g_counts[i] = 0;
}

__global__ void hist_kernel(const int* __restrict__ rows, int nE) {
    int i = blockIdx.x * blockDim.x + threadIdx.x;
    int base = i * 4;
    if (base + 4 <= nE) {
        int4 r4 = __ldcs((const int4*)(rows + base));
        atomicAdd(&g_counts[r4.x], 1);
        atomicAdd(&g_counts[r4.y], 1);
        atomicAdd(&g_counts[r4.z], 1);
        atomicAdd(&g_counts[r4.w], 1);
    } else {
        for (int e = base; e < nE; e++) atomicAdd(&g_counts[rows[e]], 1);
    }
}

// Phase A: per-block sum of 1024 counts (coalesced).
__global__ __launch_bounds__(SCAN_BLK) void scan_partial_kernel() {
    __shared__ int wsum[32];
    int tid = threadIdx.x;
    int i = blockIdx.x * SCAN_BLK + tid;
    int v = (i < N_NODES) ? g_counts[i] : 0;

    int s = v;
#pragma unroll
    for (int off = 16; off; off >>= 1) s += __shfl_down_sync(0xffffffffu, s, off);
    if ((tid & 31) == 0) wsum[tid >> 5] = s;
    __syncthreads();
    if (tid < 32) {
        int t = wsum[tid];
#pragma unroll
        for (int off = 16; off; off >>= 1) t += __shfl_down_sync(0xffffffffu, t, off);
        if (tid == 0) g_partials[blockIdx.x] = t;
    }
}

// Phase B: single small block scans the 98 partials (exclusive), writes total.
__global__ __launch_bounds__(128) void scan_partials_scan_kernel() {
    __shared__ int sp[N_SCAN_BLOCKS];
    int tid = threadIdx.x;
    if (tid < N_SCAN_BLOCKS) sp[tid] = g_partials[tid];
    __syncthreads();
    if (tid == 0) {
        int run = 0;
        for (int b = 0; b < N_SCAN_BLOCKS; b++) {
            int c = sp[b];
            sp[b] = run;
            run += c;
        }
        g_row_ptr[N_NODES] = run;
    }
    __syncthreads();
    if (tid < N_SCAN_BLOCKS) g_partials[tid] = sp[tid];
}

// Phase C: block-level exclusive scan + block offset -> row_ptr / cursor.
__global__ __launch_bounds__(SCAN_BLK) void scan_apply_kernel() {
    __shared__ int wsum[32];
    int tid = threadIdx.x;
    int lane = tid & 31;
    int wid = tid >> 5;
    int i = blockIdx.x * SCAN_BLK + tid;
    int v = (i < N_NODES) ? g_counts[i] : 0;

    int inc = v;
#pragma unroll
    for (int off = 1; off < 32; off <<= 1) {
        int n = __shfl_up_sync(0xffffffffu, inc, off);
        if (lane >= off) inc += n;
    }
    if (lane == 31) wsum[wid] = inc;
    __syncthreads();
    if (wid == 0) {
        int t = (lane < 32) ? wsum[lane] : 0;
#pragma unroll
        for (int off = 1; off < 32; off <<= 1) {
            int n = __shfl_up_sync(0xffffffffu, t, off);
            if (lane >= off) t += n;
        }
        wsum[lane] = t;
    }
    __syncthreads();

    int warp_off = (wid == 0) ? 0 : wsum[wid - 1];
    int excl = inc - v + warp_off + g_partials[blockIdx.x];
    if (i < N_NODES) {
        g_row_ptr[i] = excl;
        g_cursor[i]  = excl;
    }
}

__global__ void scatter_kernel(const int* __restrict__ rows,
                               const int* __restrict__ cols,
                               const float* __restrict__ vals,
                               int nE) {
    int i = blockIdx.x * blockDim.x + threadIdx.x;
    int base = i * 4;
    if (base + 4 <= nE) {
        int4   r4 = __ldcs((const int4*)(rows + base));
        int4   c4 = __ldcs((const int4*)(cols + base));
        float4 v4 = __ldcs((const float4*)(vals + base));
        int p0 = atomicAdd(&g_cursor[r4.x], 1);
        int p1 = atomicAdd(&g_cursor[r4.y], 1);
        int p2 = atomicAdd(&g_cursor[r4.z], 1);
        int p3 = atomicAdd(&g_cursor[r4.w], 1);
        g_edges[p0] = ((long long)__float_as_int(v4.x) << 32) | (unsigned int)c4.x;
        g_edges[p1] = ((long long)__float_as_int(v4.y) << 32) | (unsigned int)c4.y;
        g_edges[p2] = ((long long)__float_as_int(v4.z) << 32) | (unsigned int)c4.z;
        g_edges[p3] = ((long long)__float_as_int(v4.w) << 32) | (unsigned int)c4.w;
    } else {
        for (int e = base; e < nE; e++) {
            int r = rows[e];
            int pos = atomicAdd(&g_cursor[r], 1);
            g_edges[pos] = ((long long)__float_as_int(vals[e]) << 32) | (unsigned int)cols[e];
        }
    }
}

// ---------------------------------------------------------------------------
// GEMM1 (fp16 tensor, m16n8k16): h0[M,128] = x[M,256] @ W1[256,128].
// R13 proven single-buffer form; X loads streaming (__ldcs, read-once).
// ---------------------------------------------------------------------------
__global__ __launch_bounds__(256) void gemm1_fp16_kernel(const float* __restrict__ X,
                                                         const float* __restrict__ W1) {
    __shared__ __half As[128][40];   // As[m][k]
    __shared__ __half Bt[128][40];   // Bt[n][k]

    const int tid  = threadIdx.x;
    const int lane = tid & 31;
    const int warp = tid >> 5;
    const int warpM = warp >> 2;
    const int warpN = warp & 3;
    const int gid = lane >> 2;
    const int tig = lane & 3;
    const int m0 = blockIdx.x * 128;

    float acc[4][4][4];
#pragma unroll
    for (int a = 0; a < 4; a++)
#pragma unroll
        for (int b = 0; b < 4; b++)
#pragma unroll
            for (int c = 0; c < 4; c++) acc[a][b][c] = 0.f;

    for (int kc = 0; kc < IN_F; kc += 32) {
#pragma unroll
        for (int i = tid; i < 1024; i += 256) {
            int r  = i >> 3;
            int c4 = (i & 7) * 4;
            int gm = m0 + r;
            float4 v = make_float4(0.f, 0.f, 0.f, 0.f);
            if (gm < N_NODES)
                v = __ldcs((const float4*)(X + (size_t)gm * IN_F + kc + c4));
            __half2 h0 = __floats2half2_rn(v.x, v.y);
            __half2 h1 = __floats2half2_rn(v.z, v.w);
            uint2 pk;
            pk.x = *(unsigned*)&h0;
            pk.y = *(unsigned*)&h1;
            *(uint2*)&As[r][c4] = pk;
        }
#pragma unroll
        for (int i = tid; i < 1024; i += 256) {
            int n  = i & 127;
            int k4 = (i >> 7) * 4;
            float f0 = W1[(size_t)(kc + k4 + 0) * HID_F + n];
            float f1 = W1[(size_t)(kc + k4 + 1) * HID_F + n];
            float f2 = W1[(size_t)(kc + k4 + 2) * HID_F + n];
            float f3 = W1[(size_t)(kc + k4 + 3) * HID_F + n];
            __half2 h0 = __floats2half2_rn(f0, f1);
            __half2 h1 = __floats2half2_rn(f2, f3);
            uint2 pk;
            pk.x = *(unsigned*)&h0;
            pk.y = *(unsigned*)&h1;
            *(uint2*)&Bt[n][k4] = pk;
        }
        __syncthreads();

#pragma unroll
        for (int ks = 0; ks < 2; ks++) {
            const int k = ks * 16;
            unsigned afrag[4][4];
#pragma unroll
            for (int mt = 0; mt < 4; mt++) {
                int rm = warpM * 64 + mt * 16;
                afrag[mt][0] = *(unsigned*)&As[rm + gid][k + 2 * tig];
                afrag[mt][1] = *(unsigned*)&As[rm + gid + 8][k + 2 * tig];
                afrag[mt][2] = *(unsigned*)&As[rm + gid][k + 2 * tig + 8];
                afrag[mt][3] = *(unsigned*)&As[rm + gid + 8][k + 2 * tig + 8];
            }
            unsigned bfrag[4][2];
#pragma unroll
            for (int nt = 0; nt < 4; nt++) {
                int nb = warpN * 32 + nt * 8 + gid;
                bfrag[nt][0] = *(unsigned*)&Bt[nb][k + 2 * tig];
                bfrag[nt][1] = *(unsigned*)&Bt[nb][k + 2 * tig + 8];
            }
#pragma unroll
            for (int mt = 0; mt < 4; mt++)
#pragma unroll
                for (int nt = 0; nt < 4; nt++) {
                    asm volatile(
                        "mma.sync.aligned.m16n8k16.row.col.f32.f16.f16.f32 "
                        "{%0,%1,%2,%3}, {%4,%5,%6,%7}, {%8,%9}, {%0,%1,%2,%3};"
                        : "+f"(acc[mt][nt][0]), "+f"(acc[mt][nt][1]),
                          "+f"(acc[mt][nt][2]), "+f"(acc[mt][nt][3])
                        : "r"(afrag[mt][0]), "r"(afrag[mt][1]),
                          "r"(afrag[mt][2]), "r"(afrag[mt][3]),
                          "r"(bfrag[nt][0]), "r"(bfrag[nt][1]));
                }
        }
        __syncthreads();
    }

#pragma unroll
    for (int mt = 0; mt < 4; mt++) {
#pragma unroll
        for (int nt = 0; nt < 4; nt++) {
            int col = warpN * 32 + nt * 8 + 2 * tig;
            int r0 = m0 + warpM * 64 + mt * 16 + gid;
            int r1 = r0 + 8;
            if (r0 < N_NODES) {
                __half2 h = __floats2half2_rn(acc[mt][nt][0], acc[mt][nt][1]);
                *(__half2*)(g_h0h + (size_t)r0 * HID_F + col) = h;
            }
            if (r1 < N_NODES) {
                __half2 h = __floats2half2_rn(acc[mt][nt][2], acc[mt][nt][3]);
                *(__half2*)(g_h0h + (size_t)r1 * HID_F + col) = h;
            }
        }
    }
}

// ---------------------------------------------------------------------------
// SpMM1 gather (F=128, fp16 payload) — R13 form.
// ---------------------------------------------------------------------------
__device__ __forceinline__ void fma_h4(float4& acc, uint2 m, float v) {
    float2 f0 = __half22float2(*(__half2*)&m.x);
    float2 f1 = __half22float2(*(__half2*)&m.y);
    acc.x = fmaf(f0.x, v, acc.x);
    acc.y = fmaf(f0.y, v, acc.y);
    acc.z = fmaf(f1.x, v, acc.z);
    acc.w = fmaf(f1.y, v, acc.w);
}

__global__ __launch_bounds__(256) void spmm128_csr_kernel() {
    int row = blockIdx.x * 8 + (threadIdx.x >> 5);
    if (row >= N_NODES) return;
    int lane = threadIdx.x & 31;

    int e  = __ldg(&g_row_ptr[row]);
    int e1 = __ldg(&g_row_ptr[row + 1]);

    float4 acc = make_float4(0.f, 0.f, 0.f, 0.f);

    for (; e + 4 <= e1; e += 4) {
        long long p0 = __ldg(&g_edges[e + 0]);
        long long p1 = __ldg(&g_edges[e + 1]);
        long long p2 = __ldg(&g_edges[e + 2]);
        long long p3 = __ldg(&g_edges[e + 3]);
        uint2 m0 = *((const uint2*)(g_h0h + (size_t)(unsigned int)(p0 & 0xffffffffLL) * HID_F) + lane);
        uint2 m1 = *((const uint2*)(g_h0h + (size_t)(unsigned int)(p1 & 0xffffffffLL) * HID_F) + lane);
        uint2 m2 = *((const uint2*)(g_h0h + (size_t)(unsigned int)(p2 & 0xffffffffLL) * HID_F) + lane);
        uint2 m3 = *((const uint2*)(g_h0h + (size_t)(unsigned int)(p3 & 0xffffffffLL) * HID_F) + lane);
        fma_h4(acc, m0, __int_as_float((int)(p0 >> 32)));
        fma_h4(acc, m1, __int_as_float((int)(p1 >> 32)));
        fma_h4(acc, m2, __int_as_float((int)(p2 >> 32)));
        fma_h4(acc, m3, __int_as_float((int)(p3 >> 32)));
    }
    for (; e < e1; e++) {
        long long pk = __ldg(&g_edges[e]);
        int c  = (int)(unsigned int)(pk & 0xffffffffLL);
        uint2 m = *((const uint2*)(g_h0h + (size_t)c * HID_F) + lane);
        fma_h4(acc, m, __int_as_float((int)(pk >> 32)));
    }

    __half2 o0 = __floats2half2_rn(acc.x, acc.y);
    __half2 o1 = __floats2half2_rn(acc.z, acc.w);
    uint2 pk;
    pk.x = *(unsigned*)&o0;
    pk.y = *(unsigned*)&o1;
    *((uint2*)(g_h1h + (size_t)row * HID_F) + lane) = pk;
}

// ---------------------------------------------------------------------------
// GEMM2: g_h2h[M,32] = fp16( relu(g_h1h)[M,128] @ W2[128,32] ), fp16 input.
// ---------------------------------------------------------------------------
__global__ __launch_bounds__(256) void gemm2_kernel(const float* __restrict__ W2) {
    __shared__ float Ws[HID_F * OUT_F];
    for (int i = threadIdx.x; i < HID_F * OUT_F; i += 256) Ws[i] = W2[i];
    __syncthreads();

    int r = blockIdx.x * 256 + threadIdx.x;
    if (r >= N_NODES) return;

    float acc[OUT_F];
#pragma unroll
    for (int n = 0; n < OUT_F; n++) acc[n] = 0.f;

    const uint2* hp = (const uint2*)(g_h1h + (size_t)r * HID_F);
#pragma unroll 4
    for (int k4 = 0; k4 < HID_F / 4; k4++) {
        uint2 u = hp[k4];
        float2 f0 = __half22float2(*(__half2*)&u.x);
        float2 f1 = __half22float2(*(__half2*)&u.y);
        float hh[4];
        hh[0] = fmaxf(f0.x, 0.f);
        hh[1] = fmaxf(f0.y, 0.f);
        hh[2] = fmaxf(f1.x, 0.f);
        hh[3] = fmaxf(f1.y, 0.f);
        int k = k4 * 4;
#pragma unroll
        for (int dk = 0; dk < 4; dk++) {
#pragma unroll
            for (int n = 0; n < OUT_F; n += 4) {
                float4 w = *(const float4*)&Ws[(k + dk) * OUT_F + n];
                acc[n + 0] = fmaf(hh[dk], w.x, acc[n + 0]);
                acc[n + 1] = fmaf(hh[dk], w.y, acc[n + 1]);
                acc[n + 2] = fmaf(hh[dk], w.z, acc[n + 2]);
                acc[n + 3] = fmaf(hh[dk], w.w, acc[n + 3]);
            }
        }
    }

    __half2 hb[OUT_F / 2];
#pragma unroll
    for (int n = 0; n < OUT_F / 2; n++)
        hb[n] = __floats2half2_rn(acc[2 * n], acc[2 * n + 1]);
    uint4* op = (uint4*)(g_h2h + (size_t)r * OUT_F);
#pragma unroll
    for (int q = 0; q < 4; q++)
        op[q] = ((uint4*)hb)[q];
}

// ---------------------------------------------------------------------------
// SpMM2 gather (F=32, fp16 payload) — R13 form.
// ---------------------------------------------------------------------------
__global__ __launch_bounds__(256) void spmm32_csr_kernel(float* __restrict__ out) {
    int row = blockIdx.x * 32 + (threadIdx.x >> 3);
    if (row >= N_NODES) return;
    int lane = threadIdx.x & 7;

    int e  = __ldg(&g_row_ptr[row]);
    int e1 = __ldg(&g_row_ptr[row + 1]);

    float4 acc = make_float4(0.f, 0.f, 0.f, 0.f);

    for (; e + 4 <= e1; e += 4) {
        long long p0 = __ldg(&g_edges[e + 0]);
        long long p1 = __ldg(&g_edges[e + 1]);
        long long p2 = __ldg(&g_edges[e + 2]);
        long long p3 = __ldg(&g_edges[e + 3]);
        uint2 m0 = *((const uint2*)(g_h2h + (size_t)(unsigned int)(p0 & 0xffffffffLL) * OUT_F) + lane);
        uint2 m1 = *((const uint2*)(g_h2h + (size_t)(unsigned int)(p1 & 0xffffffffLL) * OUT_F) + lane);
        uint2 m2 = *((const uint2*)(g_h2h + (size_t)(unsigned int)(p2 & 0xffffffffLL) * OUT_F) + lane);
        uint2 m3 = *((const uint2*)(g_h2h + (size_t)(unsigned int)(p3 & 0xffffffffLL) * OUT_F) + lane);
        fma_h4(acc, m0, __int_as_float((int)(p0 >> 32)));
        fma_h4(acc, m1, __int_as_float((int)(p1 >> 32)));
        fma_h4(acc, m2, __int_as_float((int)(p2 >> 32)));
        fma_h4(acc, m3, __int_as_float((int)(p3 >> 32)));
    }
    for (; e < e1; e++) {
        long long pk = __ldg(&g_edges[e]);
        int c  = (int)(unsigned int)(pk & 0xffffffffLL);
        uint2 m = *((const uint2*)(g_h2h + (size_t)c * OUT_F) + lane);
        fma_h4(acc, m, __int_as_float((int)(pk >> 32)));
    }
    *((float4*)(out + (size_t)row * OUT_F) + lane) = acc;
}

// ---------------------------------------------------------------------------
// Launch. Fork-join: CSR build chain on a side stream concurrent with GEMM1.
// Inputs (metadata order): x, adj_rows, adj_cols, adj_vals, W1, W2
// ---------------------------------------------------------------------------
extern "C" void kernel_launch(void* const* d_in, const int* in_sizes, int n_in,
                              void* d_out, int out_size) {
    const float* x    = (const float*)d_in[0];
    const int*   rows = (const int*)d_in[1];
    const int*   cols = (const int*)d_in[2];
    const float* vals = (const float*)d_in[3];
    const float* W1   = (const float*)d_in[4];
    const float* W2   = (const float*)d_in[5];
    float* out = (float*)d_out;

    const int nE = in_sizes[1];

    static cudaStream_t s_side = nullptr;
    static cudaEvent_t  e_fork = nullptr;
    static cudaEvent_t  e_join = nullptr;
    if (s_side == nullptr) {
        cudaStreamCreateWithFlags(&s_side, cudaStreamNonBlocking);
        cudaEventCreateWithFlags(&e_fork, cudaEventDisableTiming);
        cudaEventCreateWithFlags(&e_join, cudaEventDisableTiming);
    }

    cudaEventRecord(e_fork, 0);
    cudaStreamWaitEvent(s_side, e_fork, 0);

    // --- Side stream: CSR build chain ---
    zero_counts_kernel<<<(N_NODES + 255) / 256, 256, 0, s_side>>>();
    hist_kernel<<<(nE / 4 + 255) / 256, 256, 0, s_side>>>(rows, nE);
    scan_partial_kernel<<<N_SCAN_BLOCKS, SCAN_BLK, 0, s_side>>>();
    scan_partials_scan_kernel<<<1, 128, 0, s_side>>>();
    scan_apply_kernel<<<N_SCAN_BLOCKS, SCAN_BLK, 0, s_side>>>();
    scatter_kernel<<<(nE / 4 + 255) / 256, 256, 0, s_side>>>(rows, cols, vals, nE);
    cudaEventRecord(e_join, s_side);

    // --- Main stream (concurrent): GEMM1 ---
    gemm1_fp16_kernel<<<(N_NODES + 127) / 128, 256>>>(x, W1);

    cudaStreamWaitEvent(0, e_join, 0);

    // SpMM1: h1 = A_hat @ h0  (fp16 gather, fp32 accum, fp16 store)
    spmm128_csr_kernel<<<(N_NODES + 7) / 8, 256>>>();

    // GEMM2: h2 = relu(h1) @ W2 (fp16 in/out)
    gemm2_kernel<<<(N_NODES + 255) / 256, 256>>>(W2);

    // SpMM2: out = A_hat @ h2  (fp16 gather, fp32 accum)
    spmm32_csr_kernel<<<(N_NODES + 31) / 32, 256>>>(out);
}